// round 16
// baseline (speedup 1.0000x reference)
#include <cuda_runtime.h>
#include <cuda_bf16.h>
#include <cuda_fp16.h>
#include <math.h>
#include <stdint.h>

#define Bsz 4
#define SEQ 4096
#define WID 768
#define NH  12
#define MBm 16
#define NBt 256           // SEQ / MBm
#define EPSV 1e-6f
#define MTOT (Bsz*SEQ)    // 16384
#define WW   (WID*WID)

// ------------------------- scratch (device globals) -------------------------
__device__ __align__(16) float g_xqk [Bsz*SEQ*WID];
__device__ __align__(16) float g_xv  [Bsz*SEQ*WID];
__device__ __align__(16) float g_gate[Bsz*SEQ*WID];
__device__ __align__(16) float g_ttt [Bsz*SEQ*WID];
__device__ __align__(16) float g_lr  [Bsz*NH*SEQ];
__device__ __align__(16) __half g_hh[Bsz*SEQ*WID];   // hidden fp16
__device__ __align__(16) __half g_th[Bsz*SEQ*WID];   // gate*z fp16
__device__ __align__(16) __half g_wt[4*WW];          // {wq,wv,wg} stacked, wo — [n][k] fp16

// ------------------------- helpers -------------------------
__device__ __forceinline__ uint32_t smem_u32(const void* p) {
    uint32_t a;
    asm("{ .reg .u64 t; cvta.to.shared.u64 t, %1; cvt.u32.u64 %0, t; }" : "=r"(a) : "l"(p));
    return a;
}
__device__ __forceinline__ float wred(float v) {
#pragma unroll
    for (int o = 16; o; o >>= 1) v += __shfl_xor_sync(0xffffffffu, v, o);
    return v;
}
__device__ __forceinline__ float hred(float v) {
#pragma unroll
    for (int o = 8; o; o >>= 1) v += __shfl_xor_sync(0xffffffffu, v, o);
    return v;
}
__device__ __forceinline__ void cpa16(uint32_t saddr, const void* g) {
    asm volatile("cp.async.cg.shared.global [%0], [%1], 16;" :: "r"(saddr), "l"(g) : "memory");
}
__device__ __forceinline__ void cpa_commit() {
    asm volatile("cp.async.commit_group;" ::: "memory");
}
__device__ __forceinline__ void ldsm4(uint32_t& r0, uint32_t& r1, uint32_t& r2, uint32_t& r3, uint32_t a) {
    asm volatile("ldmatrix.sync.aligned.m8n8.x4.shared.b16 {%0,%1,%2,%3}, [%4];"
                 : "=r"(r0), "=r"(r1), "=r"(r2), "=r"(r3) : "r"(a));
}
__device__ __forceinline__ void ldsm4t(uint32_t& r0, uint32_t& r1, uint32_t& r2, uint32_t& r3, uint32_t a) {
    asm volatile("ldmatrix.sync.aligned.m8n8.x4.trans.shared.b16 {%0,%1,%2,%3}, [%4];"
                 : "=r"(r0), "=r"(r1), "=r"(r2), "=r"(r3) : "r"(a));
}
__device__ __forceinline__ void ldsm2t(uint32_t& r0, uint32_t& r1, uint32_t a) {
    asm volatile("ldmatrix.sync.aligned.m8n8.x2.trans.shared.b16 {%0,%1}, [%2];"
                 : "=r"(r0), "=r"(r1) : "r"(a));
}
// bf16 mma (scan)
__device__ __forceinline__ void mma16816(float* c, const uint32_t* a, const uint32_t* b) {
    asm volatile("mma.sync.aligned.m16n8k16.row.col.f32.bf16.bf16.f32 "
                 "{%0,%1,%2,%3}, {%4,%5,%6,%7}, {%8,%9}, {%0,%1,%2,%3};"
                 : "+f"(c[0]), "+f"(c[1]), "+f"(c[2]), "+f"(c[3])
                 : "r"(a[0]), "r"(a[1]), "r"(a[2]), "r"(a[3]), "r"(b[0]), "r"(b[1]));
}
// fp16 mma (big GEMMs)
__device__ __forceinline__ void mma16816h(float* c, const uint32_t* a, const uint32_t* b) {
    asm volatile("mma.sync.aligned.m16n8k16.row.col.f32.f16.f16.f32 "
                 "{%0,%1,%2,%3}, {%4,%5,%6,%7}, {%8,%9}, {%0,%1,%2,%3};"
                 : "+f"(c[0]), "+f"(c[1]), "+f"(c[2]), "+f"(c[3])
                 : "r"(a[0]), "r"(a[1]), "r"(a[2]), "r"(a[3]), "r"(b[0]), "r"(b[1]));
}
// pack2(lo,hi): bf16x2 with low half = bf(lo), high = bf(hi)
__device__ __forceinline__ uint32_t pack2(float lo, float hi) {
    uint32_t r;
    asm("cvt.rn.bf16x2.f32 %0, %1, %2;" : "=r"(r) : "f"(hi), "f"(lo));
    return r;
}
__device__ __forceinline__ float bflo(uint32_t p) { return __uint_as_float(p << 16); }
__device__ __forceinline__ float bfhi(uint32_t p) { return __uint_as_float(p & 0xffff0000u); }
__device__ __forceinline__ uint32_t packh2(float lo, float hi) {
    __half2 v(__float2half_rn(lo), __float2half_rn(hi));
    return *(uint32_t*)&v;
}

// --------- prep: lr logits + weight cvt + hidden fp16 cvt (one launch) ------
__global__ __launch_bounds__(256) void prep_kernel(
    const float* __restrict__ hidden, const float* __restrict__ lrk,
    const float* __restrict__ lrb,
    const float* __restrict__ w0, const float* __restrict__ w1,
    const float* __restrict__ w2, const float* __restrict__ w3)
{
    __shared__ float sk[NH * WID];
    __shared__ float tile[32][33];
    const int tid = threadIdx.x;

    if (blockIdx.x < 2048) {
        for (int i = tid; i < NH * WID; i += 256) sk[i] = lrk[i];
        __syncthreads();
        const int gw = blockIdx.x * 8 + (tid >> 5);
        const int lane = tid & 31;
        const float* hrow = hidden + (size_t)gw * WID;
        float acc[NH];
#pragma unroll
        for (int h = 0; h < NH; h++) acc[h] = 0.f;
        for (int w = lane; w < WID; w += 32) {
            float hv = hrow[w];
#pragma unroll
            for (int h = 0; h < NH; h++) acc[h] += hv * sk[h * WID + w];
        }
        const int b = gw >> 12, n = gw & (SEQ - 1);
#pragma unroll
        for (int h = 0; h < NH; h++) {
            float v = wred(acc[h]);
            if (lane == 0) {
                float x = v + lrb[h];
                g_lr[(size_t)(b * NH + h) * SEQ + n] = (1.f / (1.f + expf(-x))) * (1.f / 64.f);
            }
        }
    } else if (blockIdx.x < 2048 + 4 * 576) {
        const int bi = blockIdx.x - 2048;
        const int z = bi / 576;
        const int rem = bi % 576;
        const float* w = (z == 0) ? w0 : (z == 1) ? w1 : (z == 2) ? w2 : w3;
        __half* th = g_wt + (size_t)z * WW;
        const int bx = (rem % 24) * 32;
        const int by = (rem / 24) * 32;
        const int x = tid & 31, y = tid >> 5;
#pragma unroll
        for (int j = 0; j < 4; j++)
            tile[y + j * 8][x] = w[(size_t)(by + y + j * 8) * WID + bx + x];
        __syncthreads();
#pragma unroll
        for (int j = 0; j < 4; j++) {
            float v = tile[x][y + j * 8];
            th[(size_t)(bx + y + j * 8) * WID + by + x] = __float2half_rn(v);
        }
    } else {
        const int i = (blockIdx.x - 2048 - 4 * 576) * 256 + tid;
        float4 v = ((const float4*)hidden)[i];
        ((uint2*)g_hh)[i] = make_uint2(packh2(v.x, v.y), packh2(v.z, v.w));
    }
}

// ------------------------- fp16 GEMM via mma.sync, BK=64 ---------------------
#define TSTRIDE 72
#define TILEB  (128*TSTRIDE*2)
#define STAGEB (2*TILEB)

__global__ __launch_bounds__(256) void mma_gemm_kernel(
    const __half* __restrict__ Ah, const __half* __restrict__ Bh,
    float* __restrict__ C0, float* __restrict__ C1, float* __restrict__ C2)
{
    extern __shared__ char smem[];
    const uint32_t sb = smem_u32(smem);
    const int tid = threadIdx.x, wid = tid >> 5, lane = tid & 31;
    const int bm = blockIdx.y * 128;
    const int bn = blockIdx.x * 128;
    const int buf = blockIdx.x / 6;
    const int coloff = (blockIdx.x % 6) * 128;
    float* C = (buf == 0) ? C0 : (buf == 1) ? C1 : C2;
    const int warpM = wid & 3, warpN = wid >> 2;

    const __half* srcs[2] = { Ah + (size_t)bm * WID, Bh + (size_t)bn * WID };

    auto load_stage = [&](int st, int k0) {
#pragma unroll
        for (int t = 0; t < 2; t++) {
#pragma unroll
            for (int rep = 0; rep < 4; rep++) {
                int li = tid + rep * 256;
                int row = li >> 3, cc = li & 7;
                const void* g = srcs[t] + (size_t)row * WID + k0 + cc * 8;
                uint32_t sa = sb + st * STAGEB + t * TILEB + row * (TSTRIDE * 2) + cc * 16;
                cpa16(sa, g);
            }
        }
        cpa_commit();
    };

    float acc[2][8][4];
#pragma unroll
    for (int i = 0; i < 2; i++)
#pragma unroll
        for (int j = 0; j < 8; j++)
#pragma unroll
            for (int k = 0; k < 4; k++) acc[i][j][k] = 0.f;

    load_stage(0, 0);

    const int NK = WID / 64;
    for (int kt = 0; kt < NK; kt++) {
        asm volatile("cp.async.wait_group 0;" ::: "memory");
        __syncthreads();
        if (kt + 1 < NK) load_stage((kt + 1) & 1, (kt + 1) * 64);

        const uint32_t base = sb + (kt & 1) * STAGEB;
        const int lrow = lane & 15;
        const int lcol = (lane & 16) ? 8 : 0;

#pragma unroll
        for (int kk = 0; kk < 4; kk++) {
            const int kb = kk * 16;
            uint32_t ah[2][4], bhf[8][2];
#pragma unroll
            for (int mt = 0; mt < 2; mt++) {
                uint32_t off = (uint32_t)((warpM * 32 + mt * 16 + lrow) * TSTRIDE + kb + lcol) * 2;
                ldsm4(ah[mt][0], ah[mt][1], ah[mt][2], ah[mt][3], base + off);
            }
#pragma unroll
            for (int ng = 0; ng < 4; ng++) {
                uint32_t off = (uint32_t)((warpN * 64 + ng * 16 + lrow) * TSTRIDE + kb + lcol) * 2;
                uint32_t r0, r1, r2, r3;
                ldsm4(r0, r1, r2, r3, base + TILEB + off);
                bhf[ng * 2][0] = r0; bhf[ng * 2 + 1][0] = r1;
                bhf[ng * 2][1] = r2; bhf[ng * 2 + 1][1] = r3;
            }
#pragma unroll
            for (int mt = 0; mt < 2; mt++)
#pragma unroll
                for (int nt = 0; nt < 8; nt++)
                    mma16816h(acc[mt][nt], ah[mt], bhf[nt]);
        }
    }

    const int r0 = bm + warpM * 32 + (lane >> 2);
    const int cb = coloff + warpN * 64 + 2 * (lane & 3);
#pragma unroll
    for (int mt = 0; mt < 2; mt++)
#pragma unroll
        for (int nt = 0; nt < 8; nt++) {
            int row = r0 + mt * 16, col = cb + nt * 8;
            *(float2*)(C + (size_t)row * WID + col) = make_float2(acc[mt][nt][0], acc[mt][nt][1]);
            *(float2*)(C + (size_t)(row + 8) * WID + col) = make_float2(acc[mt][nt][2], acc[mt][nt][3]);
        }
}

// ------------------------- TTT scan (256 threads, 3 barriers/step) ----------
// R15 + Attn fused into the Z-GEMM ks-loop for warps 0,1 (fragment reuse).
#define SCAN_SMEM (4496*4 + (2*4608 + 2*4*1152 + 4*1152 + 2*384)*2)

__global__ __launch_bounds__(256) void ttt_scan_kernel(
    const float* __restrict__ W1in, const float* __restrict__ b1in,
    const float* __restrict__ gin,  const float* __restrict__ bbin,
    const float* __restrict__ lti,
    const float* __restrict__ cqk, const float* __restrict__ cqb,
    const float* __restrict__ ckk, const float* __restrict__ ckb)
{
    extern __shared__ float sm[];
    float* sZ   = sm + 1088;          // [16][68]
    float* sZbB = sm + 2176;          // [2][16][68]
    float* b1s  = sm + 4352;          // [64]
    float* lrB  = sm + 4416;          // [2][16]
    float* lrwB = sm + 4448;          // [2][16]
    float* toki = sm + 4480;          // [16]
    __nv_bfloat16* W1h = (__nv_bfloat16*)(sm + 4496);  // [64 k][72 d]
    __nv_bfloat16* W1l = W1h + 4608;
    __nv_bfloat16* KQ  = W1l + 4608;                   // [2][4][16*72]
    __nv_bfloat16* sPh = KQ + 2 * 4608;
    __nv_bfloat16* sPl = sPh + 1152;
    __nv_bfloat16* sWGh= sPl + 1152;
    __nv_bfloat16* sWGl= sWGh + 1152;
    __nv_bfloat16* CfH = sWGl + 1152;                  // [16 i][24 m]
    __nv_bfloat16* CfL = CfH + 384;

    const uint32_t uKQ0 = smem_u32(KQ);
    const uint32_t uKQ1 = uKQ0 + 4608 * 2;
    const uint32_t uWh = smem_u32(W1h), uWl = smem_u32(W1l);
    const uint32_t uPh = smem_u32(sPh), uPl = smem_u32(sPl);
    const uint32_t uGh = smem_u32(sWGh), uGl = smem_u32(sWGl);
    const uint32_t uCfH = smem_u32(CfH), uCfL = smem_u32(CfL);

    const int tid = threadIdx.x;
    const int bh = blockIdx.x;
    const int b = bh / NH, h = bh % NH;
    const int lane = tid & 31, wid = tid >> 5;
    const int r  = tid >> 4;
    const int cg = tid & 15;
    const int c0 = cg * 4;

    for (int i = tid; i < 4096; i += 256) {
        int k = i >> 6, d = i & 63;
        float v = W1in[h * 4096 + i];
        __nv_bfloat16 hi = __float2bfloat16(v);
        W1h[k * 72 + d] = hi;
        W1l[k * 72 + d] = __float2bfloat16(v - __bfloat162float(hi));
    }
    if (tid < 64) b1s[tid] = b1in[h * 64 + tid];
    if (tid < 16) toki[tid] = fmaxf(1.f / (float)(tid + 1) + lti[tid], 0.f);

    const int n0w = wid * 8;
    const int krw = lane >> 2;
    const int dcw = n0w + 2 * (lane & 3);
    const int drow = lane >> 2;
    float cw[4][4];
#pragma unroll
    for (int mt = 0; mt < 4; mt++) {
        const float* wsrc = W1in + h * 4096 + (mt * 16 + krw) * 64 + dcw;
        cw[mt][0] = wsrc[0];        cw[mt][1] = wsrc[1];
        cw[mt][2] = wsrc[8 * 64];   cw[mt][3] = wsrc[8 * 64 + 1];
    }

    const size_t gb2 = (size_t)b * SEQ * WID + h * 64 + c0;
    const float* lrp = g_lr + (size_t)bh * SEQ;

    float4 wq0 = *(const float4*)(cqk + 0 * WID + h * 64 + c0);
    float4 wq1 = *(const float4*)(cqk + 1 * WID + h * 64 + c0);
    float4 wq2 = *(const float4*)(cqk + 2 * WID + h * 64 + c0);
    float4 wq3 = *(const float4*)(cqk + 3 * WID + h * 64 + c0);
    float4 wk0 = *(const float4*)(ckk + 0 * WID + h * 64 + c0);
    float4 wk1 = *(const float4*)(ckk + 1 * WID + h * 64 + c0);
    float4 wk2 = *(const float4*)(ckk + 2 * WID + h * 64 + c0);
    float4 wk3 = *(const float4*)(ckk + 3 * WID + h * 64 + c0);
    float4 qb4 = *(const float4*)(cqb + h * 64 + c0);
    float4 kb4 = *(const float4*)(ckb + h * 64 + c0);
    int j0 = c0 >> 1;
    float f0 = expf(-9.210340371976184f * (float)j0 * (1.f / 32.f));
    float f1 = expf(-9.210340371976184f * (float)(j0 + 1) * (1.f / 32.f));
    const float cs0 = cosf((float)r * f0), sn0 = sinf((float)r * f0);
    const float cs1 = cosf((float)r * f1), sn1 = sinf((float)r * f1);
    const float gv0 = gin[h * 64 + c0],     gv1 = gin[h * 64 + c0 + 1];
    const float gv2 = gin[h * 64 + c0 + 2], gv3 = gin[h * 64 + c0 + 3];
    const float bv0 = bbin[h * 64 + c0],     bv1 = bbin[h * 64 + c0 + 1];
    const float bv2 = bbin[h * 64 + c0 + 2], bv3 = bbin[h * 64 + c0 + 3];

    __syncthreads();
    const float toki15 = toki[15];

    float4 x0n = make_float4(0, 0, 0, 0), x1n = x0n, x2n = x0n, x3n = x0n;
    if (r >= 3) x0n = *(const float4*)(g_xqk + gb2 + (size_t)(r - 3) * WID);
    if (r >= 2) x1n = *(const float4*)(g_xqk + gb2 + (size_t)(r - 2) * WID);
    if (r >= 1) x2n = *(const float4*)(g_xqk + gb2 + (size_t)(r - 1) * WID);
    x3n = *(const float4*)(g_xqk + gb2 + (size_t)r * WID);
    float4 v4n = *(const float4*)(g_xv + gb2 + (size_t)r * WID);
    float lrn = (tid < 16) ? lrp[tid] : 0.f;

    float4 q4c, t4c, q4prev = make_float4(0, 0, 0, 0);
    uint32_t kp0, kp1, klp0, klp1, qp0, qp1, qlp0, qlp1;
    {
        float4 q, k;
        q.x = qb4.x + x0n.x * wq0.x + x1n.x * wq1.x + x2n.x * wq2.x + x3n.x * wq3.x;
        q.y = qb4.y + x0n.y * wq0.y + x1n.y * wq1.y + x2n.y * wq2.y + x3n.y * wq3.y;
        q.z = qb4.z + x0n.z * wq0.z + x1n.z * wq1.z + x2n.z * wq2.z + x3n.z * wq3.z;
        q.w = qb4.w + x0n.w * wq0.w + x1n.w * wq1.w + x2n.w * wq2.w + x3n.w * wq3.w;
        k.x = kb4.x + x0n.x * wk0.x + x1n.x * wk1.x + x2n.x * wk2.x + x3n.x * wk3.x;
        k.y = kb4.y + x0n.y * wk0.y + x1n.y * wk1.y + x2n.y * wk2.y + x3n.y * wk3.y;
        k.z = kb4.z + x0n.z * wk0.z + x1n.z * wk1.z + x2n.z * wk2.z + x3n.z * wk3.z;
        k.w = kb4.w + x0n.w * wk0.w + x1n.w * wk1.w + x2n.w * wk2.w + x3n.w * wk3.w;
        float4 qr, kr;
        qr.x = q.x * cs0 - q.y * sn0; qr.y = q.x * sn0 + q.y * cs0;
        qr.z = q.z * cs1 - q.w * sn1; qr.w = q.z * sn1 + q.w * cs1;
        kr.x = k.x * cs0 - k.y * sn0; kr.y = k.x * sn0 + k.y * cs0;
        kr.z = k.z * cs1 - k.w * sn1; kr.w = k.z * sn1 + k.w * cs1;
        kp0 = pack2(kr.x, kr.y); kp1 = pack2(kr.z, kr.w);
        klp0 = pack2(kr.x - bflo(kp0), kr.y - bfhi(kp0));
        klp1 = pack2(kr.z - bflo(kp1), kr.w - bfhi(kp1));
        qp0 = pack2(qr.x, qr.y); qp1 = pack2(qr.z, qr.w);
        qlp0 = pack2(qr.x - bflo(qp0), qr.y - bfhi(qp0));
        qlp1 = pack2(qr.z - bflo(qp1), qr.w - bfhi(qp1));
        q4c = qr;
        t4c = make_float4(v4n.x - kr.x, v4n.y - kr.y, v4n.z - kr.z, v4n.w - kr.w);
    }

    for (int nb = 0; nb < NBt; nb++) {
        const int buf = nb & 1;
        const uint32_t uB  = buf ? uKQ1 : uKQ0;
        const uint32_t uKh = uB, uKl = uB + 1152 * 2;
        const uint32_t uQh = uB + 2304 * 2, uQl = uB + 3456 * 2;
        __nv_bfloat16* sKh = KQ + buf * 4608;
        __nv_bfloat16* sKl = sKh + 1152;
        __nv_bfloat16* sQh = sKl + 1152;
        __nv_bfloat16* sQl = sQh + 1152;
        float* lr  = lrB  + buf * 16;
        float* lrw = lrwB + buf * 16;
        float* sZb = sZbB + buf * 1088;
        float* sZbPrev = sZbB + (buf ^ 1) * 1088;

        *(uint2*)(sKh + r * 72 + c0) = make_uint2(kp0, kp1);
        *(uint2*)(sKl + r * 72 + c0) = make_uint2(klp0, klp1);
        *(uint2*)(sQh + r * 72 + c0) = make_uint2(qp0, qp1);
        *(uint2*)(sQl + r * 72 + c0) = make_uint2(qlp0, qlp1);
        if (tid < 16) { lr[tid] = lrn; lrw[tid] = toki15 * lrn; }
        if (nb > 0) {
            float4 y4 = *(const float4*)(sZbPrev + r * 68 + c0);
            float s = hred(y4.x + y4.y + y4.z + y4.w);
            float qq = hred(y4.x * y4.x + y4.y * y4.y + y4.z * y4.z + y4.w * y4.w);
            float m = s * (1.f / 64.f);
            float rstd = rsqrtf(qq * (1.f / 64.f) - m * m + EPSV);
            float4 o;
            o.x = q4prev.x + gv0 * ((y4.x - m) * rstd) + bv0;
            o.y = q4prev.y + gv1 * ((y4.y - m) * rstd) + bv1;
            o.z = q4prev.z + gv2 * ((y4.z - m) * rstd) + bv2;
            o.w = q4prev.w + gv3 * ((y4.w - m) * rstd) + bv3;
            *(float4*)(g_ttt + gb2 + (size_t)((nb - 1) * MBm + r) * WID) = o;
        }
        __syncthreads();                                   // (B)

        if (nb + 1 < NBt) {
            const size_t rb = gb2 + (size_t)((nb + 1) * MBm + r - 3) * WID;
            x0n = *(const float4*)(g_xqk + rb);
            x1n = *(const float4*)(g_xqk + rb + WID);
            x2n = *(const float4*)(g_xqk + rb + 2 * WID);
            x3n = *(const float4*)(g_xqk + rb + 3 * WID);
            v4n = *(const float4*)(g_xv + rb + 3 * WID);
            if (tid < 16) lrn = lrp[(nb + 1) * MBm + tid];
        }

        // Z GEMM (all warps) with Attn fused for warps 0,1 (fragment reuse)
        float zq[4];
        {
            float zk[4];
            float at[4] = {0.f, 0.f, 0.f, 0.f};
            float bA = b1s[dcw], bB = b1s[dcw + 1];
            zk[0] = bA; zk[1] = bB; zk[2] = bA; zk[3] = bB;
            zq[0] = bA; zq[1] = bB; zq[2] = bA; zq[3] = bB;
            const int la = lane & 15;
#pragma unroll
            for (int ks = 0; ks < 4; ks++) {
                const int kb = ks * 16;
                uint32_t aoff = (uint32_t)(la * 72 + kb + (lane >> 4) * 8) * 2;
                uint32_t boff = (uint32_t)((kb + la) * 72 + n0w) * 2;
                uint32_t akh[4], akl[4], aqh[4], aql[4], bhf[2], blf[2];
                ldsm4(akh[0], akh[1], akh[2], akh[3], uKh + aoff);
                ldsm4(akl[0], akl[1], akl[2], akl[3], uKl + aoff);
                ldsm4(aqh[0], aqh[1], aqh[2], aqh[3], uQh + aoff);
                ldsm4(aql[0], aql[1], aql[2], aql[3], uQl + aoff);
                ldsm2t(bhf[0], bhf[1], uWh + boff);
                ldsm2t(blf[0], blf[1], uWl + boff);
                mma16816(zk, akh, bhf);
                mma16816(zk, akh, blf);
                mma16816(zk, akl, bhf);
                mma16816(zq, aqh, bhf);
                mma16816(zq, aqh, blf);
                mma16816(zq, aql, bhf);
                if (wid < 2) {
                    uint32_t bhh[2] = { akh[wid], akh[wid + 2] };
                    uint32_t bll[2] = { akl[wid], akl[wid + 2] };
                    mma16816(at, aqh, bhh);
                    mma16816(at, aqh, bll);
                    mma16816(at, aql, bhh);
                }
            }
            *(float2*)(sZ + drow * 68 + dcw)       = make_float2(zk[0], zk[1]);
            *(float2*)(sZ + (drow + 8) * 68 + dcw) = make_float2(zk[2], zk[3]);
            // Cf pack (warps 0,1)
            if (wid < 2) {
                const int i0 = lane >> 2;
                const int m0 = wid * 8 + 2 * (lane & 3);
                float ta = toki[i0], tb = toki[i0 + 8];
                float v00 = (m0     <= i0    ) ? ta * (at[0] + 1.f) : 0.f;
                float v01 = (m0 + 1 <= i0    ) ? ta * (at[1] + 1.f) : 0.f;
                float v10 = (m0     <= i0 + 8) ? tb * (at[2] + 1.f) : 0.f;
                float v11 = (m0 + 1 <= i0 + 8) ? tb * (at[3] + 1.f) : 0.f;
                uint32_t h0 = pack2(v00, v01), h1 = pack2(v10, v11);
                *(uint32_t*)(CfH + i0 * 24 + m0)       = h0;
                *(uint32_t*)(CfH + (i0 + 8) * 24 + m0) = h1;
                *(uint32_t*)(CfL + i0 * 24 + m0)       = pack2(v00 - bflo(h0), v01 - bfhi(h0));
                *(uint32_t*)(CfL + (i0 + 8) * 24 + m0) = pack2(v10 - bflo(h1), v11 - bfhi(h1));
            }
        }
        __syncthreads();                                   // (B2)

        // LN-fused-L2-bwd; pack two bf16 grad tile sets
        {
            float4 z4 = *(const float4*)(sZ + r * 68 + c0);
            float z0 = z4.x, z1 = z4.y, z2 = z4.z, z3 = z4.w;
            float s = hred(z0 + z1 + z2 + z3);
            float qq = hred(z0 * z0 + z1 * z1 + z2 * z2 + z3 * z3);
            float m = s * (1.f / 64.f);
            float rstd = rsqrtf(qq * (1.f / 64.f) - m * m + EPSV);
            float xh0 = (z0 - m) * rstd, xh1 = (z1 - m) * rstd;
            float xh2 = (z2 - m) * rstd, xh3 = (z3 - m) * rstd;
            float gx0 = (gv0 * xh0 + bv0 - t4c.x) * gv0;
            float gx1 = (gv1 * xh1 + bv1 - t4c.y) * gv1;
            float gx2 = (gv2 * xh2 + bv2 - t4c.z) * gv2;
            float gx3 = (gv3 * xh3 + bv3 - t4c.w) * gv3;
            float s1 = hred(gx0 + gx1 + gx2 + gx3);
            float s2 = hred(gx0 * xh0 + gx1 * xh1 + gx2 * xh2 + gx3 * xh3);
            float sc = rstd * (1.f / 64.f);
            float grx = (64.f * gx0 - s1 - xh0 * s2) * sc;
            float gry = (64.f * gx1 - s1 - xh1 * s2) * sc;
            float grz = (64.f * gx2 - s1 - xh2 * s2) * sc;
            float grw = (64.f * gx3 - s1 - xh3 * s2) * sc;
            float lrr = lr[r];
            float p0 = -lrr * grx, p1 = -lrr * gry, p2 = -lrr * grz, p3 = -lrr * grw;
            uint32_t ph0 = pack2(p0, p1), ph1 = pack2(p2, p3);
            *(uint2*)(sPh + r * 72 + c0) = make_uint2(ph0, ph1);
            *(uint2*)(sPl + r * 72 + c0) = make_uint2(
                pack2(p0 - bflo(ph0), p1 - bfhi(ph0)),
                pack2(p2 - bflo(ph1), p3 - bfhi(ph1)));
            float w0 = toki15 * p0, w1 = toki15 * p1, w2 = toki15 * p2, w3 = toki15 * p3;
            uint32_t wh0 = pack2(w0, w1), wh1 = pack2(w2, w3);
            *(uint2*)(sWGh + r * 72 + c0) = make_uint2(wh0, wh1);
            *(uint2*)(sWGl + r * 72 + c0) = make_uint2(
                pack2(w0 - bflo(wh0), w1 - bfhi(wh0)),
                pack2(w2 - bflo(wh1), w3 - bfhi(wh1)));
        }
        __syncthreads();                                   // (C)

        // Z1_bar = zq + Cf_raw @ (-lr*grad)
        {
            uint32_t cfh4[4], cfl4[4], bp[2], bpl[2];
            uint32_t aoffc = (uint32_t)((lane & 15) * 24 + (lane >> 4) * 8) * 2;
            ldsm4(cfh4[0], cfh4[1], cfh4[2], cfh4[3], uCfH + aoffc);
            ldsm4(cfl4[0], cfl4[1], cfl4[2], cfl4[3], uCfL + aoffc);
            uint32_t boffp = (uint32_t)((lane & 15) * 72 + n0w) * 2;
            ldsm2t(bp[0], bp[1], uPh + boffp);
            ldsm2t(bpl[0], bpl[1], uPl + boffp);
            mma16816(zq, cfh4, bp);
            mma16816(zq, cfh4, bpl);
            mma16816(zq, cfl4, bp);
            *(float2*)(sZb + drow * 68 + dcw)       = make_float2(zq[0], zq[1]);
            *(float2*)(sZb + (drow + 8) * 68 + dcw) = make_float2(zq[2], zq[3]);
        }

        // W1 update: cw += XK^T @ (-toki15*lr*grad); bf16 writeback
        {
            uint32_t bgh[2], bgl[2];
            const uint32_t gboff = (uint32_t)((lane & 15) * 72 + n0w) * 2;
            ldsm2t(bgh[0], bgh[1], uGh + gboff);
            ldsm2t(bgl[0], bgl[1], uGl + gboff);
            const int amr = ((lane >> 4) << 3) + (lane & 7);
            const int akc = ((lane >> 3) & 1) << 3;
#pragma unroll
            for (int mt = 0; mt < 4; mt++) {
                uint32_t aoff = (uint32_t)(amr * 72 + mt * 16 + akc) * 2;
                uint32_t akh[4], akl[4];
                ldsm4t(akh[0], akh[1], akh[2], akh[3], uKh + aoff);
                ldsm4t(akl[0], akl[1], akl[2], akl[3], uKl + aoff);
                mma16816(cw[mt], akh, bgh);
                mma16816(cw[mt], akh, bgl);
                mma16816(cw[mt], akl, bgh);
            }
#pragma unroll
            for (int mt = 0; mt < 4; mt++) {
                int k0 = mt * 16 + krw;
                uint32_t h01 = pack2(cw[mt][0], cw[mt][1]);
                uint32_t h23 = pack2(cw[mt][2], cw[mt][3]);
                *(uint32_t*)(W1h + k0 * 72 + dcw)       = h01;
                *(uint32_t*)(W1h + (k0 + 8) * 72 + dcw) = h23;
                *(uint32_t*)(W1l + k0 * 72 + dcw) = pack2(
                    cw[mt][0] - bflo(h01), cw[mt][1] - bfhi(h01));
                *(uint32_t*)(W1l + (k0 + 8) * 72 + dcw) = pack2(
                    cw[mt][2] - bflo(h23), cw[mt][3] - bfhi(h23));
            }
            // b1 += colsum(WG) — threads 0..63
            if (tid < 64) {
                const int du = tid;
                float bs = 0.f;
#pragma unroll
                for (int mm = 0; mm < 16; mm++) {
                    bs += __bfloat162float(sWGh[mm * 72 + du]);
                    bs += __bfloat162float(sWGl[mm * 72 + du]);
                }
                b1s[du] += bs;
            }
        }

        // conv/rope for nb+1 (registers only)
        q4prev = q4c;
        if (nb + 1 < NBt) {
            float4 q, k;
            q.x = qb4.x + x0n.x * wq0.x + x1n.x * wq1.x + x2n.x * wq2.x + x3n.x * wq3.x;
            q.y = qb4.y + x0n.y * wq0.y + x1n.y * wq1.y + x2n.y * wq2.y + x3n.y * wq3.y;
            q.z = qb4.z + x0n.z * wq0.z + x1n.z * wq1.z + x2n.z * wq2.z + x3n.z * wq3.z;
            q.w = qb4.w + x0n.w * wq0.w + x1n.w * wq1.w + x2n.w * wq2.w + x3n.w * wq3.w;
            k.x = kb4.x + x0n.x * wk0.x + x1n.x * wk1.x + x2n.x * wk2.x + x3n.x * wk3.x;
            k.y = kb4.y + x0n.y * wk0.y + x1n.y * wk1.y + x2n.y * wk2.y + x3n.y * wk3.y;
            k.z = kb4.z + x0n.z * wk0.z + x1n.z * wk1.z + x2n.z * wk2.z + x3n.z * wk3.z;
            k.w = kb4.w + x0n.w * wk0.w + x1n.w * wk1.w + x2n.w * wk2.w + x3n.w * wk3.w;
            float4 qr, kr;
            qr.x = q.x * cs0 - q.y * sn0; qr.y = q.x * sn0 + q.y * cs0;
            qr.z = q.z * cs1 - q.w * sn1; qr.w = q.z * sn1 + q.w * cs1;
            kr.x = k.x * cs0 - k.y * sn0; kr.y = k.x * sn0 + k.y * cs0;
            kr.z = k.z * cs1 - k.w * sn1; kr.w = k.z * sn1 + k.w * cs1;
            kp0 = pack2(kr.x, kr.y); kp1 = pack2(kr.z, kr.w);
            klp0 = pack2(kr.x - bflo(kp0), kr.y - bfhi(kp0));
            klp1 = pack2(kr.z - bflo(kp1), kr.w - bfhi(kp1));
            qp0 = pack2(qr.x, qr.y); qp1 = pack2(qr.z, qr.w);
            qlp0 = pack2(qr.x - bflo(qp0), qr.y - bfhi(qp0));
            qlp1 = pack2(qr.z - bflo(qp1), qr.w - bfhi(qp1));
            q4c = qr;
            t4c = make_float4(v4n.x - kr.x, v4n.y - kr.y, v4n.z - kr.z, v4n.w - kr.w);
        }
    }

    // final output (nb = NBt-1, buffer (NBt-1)&1 = 1)
    __syncthreads();
    {
        float* sZbF = sZbB + ((NBt - 1) & 1) * 1088;
        float4 y4 = *(const float4*)(sZbF + r * 68 + c0);
        float s = hred(y4.x + y4.y + y4.z + y4.w);
        float qq = hred(y4.x * y4.x + y4.y * y4.y + y4.z * y4.z + y4.w * y4.w);
        float m = s * (1.f / 64.f);
        float rstd = rsqrtf(qq * (1.f / 64.f) - m * m + EPSV);
        float4 o;
        o.x = q4prev.x + gv0 * ((y4.x - m) * rstd) + bv0;
        o.y = q4prev.y + gv1 * ((y4.y - m) * rstd) + bv1;
        o.z = q4prev.z + gv2 * ((y4.z - m) * rstd) + bv2;
        o.w = q4prev.w + gv3 * ((y4.w - m) * rstd) + bv3;
        *(float4*)(g_ttt + gb2 + (size_t)((NBt - 1) * MBm + r) * WID) = o;
    }
}

// ------------- post: warp-per-row, no block barriers -------------------------
__global__ __launch_bounds__(256) void postfuse_kernel(
    const float* __restrict__ pns, const float* __restrict__ pnb)
{
    const int lane = threadIdx.x & 31;
    const int row = blockIdx.x * 8 + (threadIdx.x >> 5);
    const float4* o4 = (const float4*)(g_ttt + (size_t)row * WID);
    const float4* g4 = (const float4*)(g_gate + (size_t)row * WID);
    uint2* t2 = (uint2*)(g_th + (size_t)row * WID);

    float4 v[6];
    float s = 0.f, q = 0.f;
#pragma unroll
    for (int i = 0; i < 6; i++) {
        v[i] = o4[lane + 32 * i];
        s += v[i].x + v[i].y + v[i].z + v[i].w;
        q += v[i].x * v[i].x + v[i].y * v[i].y + v[i].z * v[i].z + v[i].w * v[i].w;
    }
    s = wred(s); q = wred(q);
    const float m = s * (1.f / 768.f);
    const float rs = rsqrtf(q * (1.f / 768.f) - m * m + EPSV);

#pragma unroll
    for (int i = 0; i < 6; i++) {
        const int c = (lane + 32 * i) * 4;
        float4 pn = *(const float4*)(pns + c);
        float4 pb = *(const float4*)(pnb + c);
        float4 g = g4[lane + 32 * i];
        float z0 = pn.x * ((v[i].x - m) * rs) + pb.x;
        float z1 = pn.y * ((v[i].y - m) * rs) + pb.y;
        float z2 = pn.z * ((v[i].z - m) * rs) + pb.z;
        float z3 = pn.w * ((v[i].w - m) * rs) + pb.w;
        float gl0 = 0.5f * g.x * (1.f + tanhf(0.7978845608028654f * (g.x + 0.044715f * g.x * g.x * g.x)));
        float gl1 = 0.5f * g.y * (1.f + tanhf(0.7978845608028654f * (g.y + 0.044715f * g.y * g.y * g.y)));
        float gl2 = 0.5f * g.z * (1.f + tanhf(0.7978845608028654f * (g.z + 0.044715f * g.z * g.z * g.z)));
        float gl3 = 0.5f * g.w * (1.f + tanhf(0.7978845608028654f * (g.w + 0.044715f * g.w * g.w * g.w)));
        t2[lane + 32 * i] = make_uint2(packh2(gl0 * z0, gl1 * z1), packh2(gl2 * z2, gl3 * z3));
    }
}

// ------------------------- launch --------------------------------------------
extern "C" void kernel_launch(void* const* d_in, const int* in_sizes, int n_in,
                              void* d_out, int out_size)
{
    const float* hidden = (const float*)d_in[0];
    const float* wq  = (const float*)d_in[1];
    const float* wv  = (const float*)d_in[2];
    const float* wo  = (const float*)d_in[3];
    const float* wg  = (const float*)d_in[4];
    const float* cqk = (const float*)d_in[5];
    const float* cqb = (const float*)d_in[6];
    const float* ckk = (const float*)d_in[7];
    const float* ckb = (const float*)d_in[8];
    const float* W1  = (const float*)d_in[9];
    const float* b1  = (const float*)d_in[10];
    const float* tns = (const float*)d_in[11];
    const float* tnb = (const float*)d_in[12];
    const float* lrk = (const float*)d_in[13];
    const float* lrb = (const float*)d_in[14];
    const float* lti = (const float*)d_in[15];
    const float* pns = (const float*)d_in[16];
    const float* pnb = (const float*)d_in[17];
    float* out = (float*)d_out;

    float *p_xqk, *p_xv, *p_gate;
    __half *p_hh, *p_th, *p_wt;
    cudaGetSymbolAddress((void**)&p_xqk,  g_xqk);
    cudaGetSymbolAddress((void**)&p_xv,   g_xv);
    cudaGetSymbolAddress((void**)&p_gate, g_gate);
    cudaGetSymbolAddress((void**)&p_hh,   g_hh);
    cudaGetSymbolAddress((void**)&p_th,   g_th);
    cudaGetSymbolAddress((void**)&p_wt,   g_wt);

    const int smem_mma = 2 * STAGEB;   // 73728
    cudaFuncSetAttribute(mma_gemm_kernel, cudaFuncAttributeMaxDynamicSharedMemorySize, smem_mma);
    cudaFuncSetAttribute(ttt_scan_kernel, cudaFuncAttributeMaxDynamicSharedMemorySize, SCAN_SMEM);

    // 1: lr + weight cvt + hidden cvt fused
    prep_kernel<<<2048 + 4 * 576 + MTOT * WID / 4 / 256, 256>>>(
        hidden, lrk, lrb, wq, wv, wg, wo);
    // 2: fused QVG GEMM
    {
        dim3 gg(18, MTOT / 128);
        mma_gemm_kernel<<<gg, 256, smem_mma>>>(p_hh, p_wt, p_xqk, p_xv, p_gate);
    }
    // 3: scan
    ttt_scan_kernel<<<Bsz * NH, 256, SCAN_SMEM>>>(W1, b1, tns, tnb, lti, cqk, cqb, ckk, ckb);
    // 4: post LN * gelu gate (warp-per-row)
    postfuse_kernel<<<MTOT / 8, 256>>>(pns, pnb);
    // 5: output GEMM
    {
        dim3 gg(6, MTOT / 128);
        mma_gemm_kernel<<<gg, 256, smem_mma>>>(p_th, p_wt + (size_t)3 * WW, out, out, out);
    }
}

// round 17
// speedup vs baseline: 1.0501x; 1.0501x over previous
#include <cuda_runtime.h>
#include <cuda_bf16.h>
#include <cuda_fp16.h>
#include <math.h>
#include <stdint.h>

#define Bsz 4
#define SEQ 4096
#define WID 768
#define NH  12
#define MBm 16
#define NBt 256           // SEQ / MBm
#define EPSV 1e-6f
#define MTOT (Bsz*SEQ)    // 16384
#define WW   (WID*WID)

// ------------------------- scratch (device globals) -------------------------
__device__ __align__(16) float g_xqk [Bsz*SEQ*WID];
__device__ __align__(16) float g_xv  [Bsz*SEQ*WID];
__device__ __align__(16) float g_gate[Bsz*SEQ*WID];
__device__ __align__(16) float g_ttt [Bsz*SEQ*WID];
__device__ __align__(16) float g_lr  [Bsz*NH*SEQ];
__device__ __align__(16) __half g_hh[Bsz*SEQ*WID];   // hidden fp16
__device__ __align__(16) __half g_th[Bsz*SEQ*WID];   // gate*z fp16
__device__ __align__(16) __half g_wt[4*WW];          // {wq,wv,wg} stacked, wo — [n][k] fp16

// ------------------------- helpers -------------------------
__device__ __forceinline__ uint32_t smem_u32(const void* p) {
    uint32_t a;
    asm("{ .reg .u64 t; cvta.to.shared.u64 t, %1; cvt.u32.u64 %0, t; }" : "=r"(a) : "l"(p));
    return a;
}
__device__ __forceinline__ float wred(float v) {
#pragma unroll
    for (int o = 16; o; o >>= 1) v += __shfl_xor_sync(0xffffffffu, v, o);
    return v;
}
__device__ __forceinline__ float hred(float v) {
#pragma unroll
    for (int o = 8; o; o >>= 1) v += __shfl_xor_sync(0xffffffffu, v, o);
    return v;
}
__device__ __forceinline__ void cpa16(uint32_t saddr, const void* g) {
    asm volatile("cp.async.cg.shared.global [%0], [%1], 16;" :: "r"(saddr), "l"(g) : "memory");
}
__device__ __forceinline__ void cpa_commit() {
    asm volatile("cp.async.commit_group;" ::: "memory");
}
__device__ __forceinline__ void ldsm4(uint32_t& r0, uint32_t& r1, uint32_t& r2, uint32_t& r3, uint32_t a) {
    asm volatile("ldmatrix.sync.aligned.m8n8.x4.shared.b16 {%0,%1,%2,%3}, [%4];"
                 : "=r"(r0), "=r"(r1), "=r"(r2), "=r"(r3) : "r"(a));
}
__device__ __forceinline__ void ldsm4t(uint32_t& r0, uint32_t& r1, uint32_t& r2, uint32_t& r3, uint32_t a) {
    asm volatile("ldmatrix.sync.aligned.m8n8.x4.trans.shared.b16 {%0,%1,%2,%3}, [%4];"
                 : "=r"(r0), "=r"(r1), "=r"(r2), "=r"(r3) : "r"(a));
}
__device__ __forceinline__ void ldsm2t(uint32_t& r0, uint32_t& r1, uint32_t a) {
    asm volatile("ldmatrix.sync.aligned.m8n8.x2.trans.shared.b16 {%0,%1}, [%2];"
                 : "=r"(r0), "=r"(r1) : "r"(a));
}
// bf16 mma (scan)
__device__ __forceinline__ void mma16816(float* c, const uint32_t* a, const uint32_t* b) {
    asm volatile("mma.sync.aligned.m16n8k16.row.col.f32.bf16.bf16.f32 "
                 "{%0,%1,%2,%3}, {%4,%5,%6,%7}, {%8,%9}, {%0,%1,%2,%3};"
                 : "+f"(c[0]), "+f"(c[1]), "+f"(c[2]), "+f"(c[3])
                 : "r"(a[0]), "r"(a[1]), "r"(a[2]), "r"(a[3]), "r"(b[0]), "r"(b[1]));
}
// fp16 mma (big GEMMs)
__device__ __forceinline__ void mma16816h(float* c, const uint32_t* a, const uint32_t* b) {
    asm volatile("mma.sync.aligned.m16n8k16.row.col.f32.f16.f16.f32 "
                 "{%0,%1,%2,%3}, {%4,%5,%6,%7}, {%8,%9}, {%0,%1,%2,%3};"
                 : "+f"(c[0]), "+f"(c[1]), "+f"(c[2]), "+f"(c[3])
                 : "r"(a[0]), "r"(a[1]), "r"(a[2]), "r"(a[3]), "r"(b[0]), "r"(b[1]));
}
// pack2(lo,hi): bf16x2 with low half = bf(lo), high = bf(hi)
__device__ __forceinline__ uint32_t pack2(float lo, float hi) {
    uint32_t r;
    asm("cvt.rn.bf16x2.f32 %0, %1, %2;" : "=r"(r) : "f"(hi), "f"(lo));
    return r;
}
__device__ __forceinline__ float bflo(uint32_t p) { return __uint_as_float(p << 16); }
__device__ __forceinline__ float bfhi(uint32_t p) { return __uint_as_float(p & 0xffff0000u); }
__device__ __forceinline__ uint32_t packh2(float lo, float hi) {
    __half2 v(__float2half_rn(lo), __float2half_rn(hi));
    return *(uint32_t*)&v;
}

// --------- prep: lr logits + weight cvt + hidden fp16 cvt (one launch) ------
__global__ __launch_bounds__(256) void prep_kernel(
    const float* __restrict__ hidden, const float* __restrict__ lrk,
    const float* __restrict__ lrb,
    const float* __restrict__ w0, const float* __restrict__ w1,
    const float* __restrict__ w2, const float* __restrict__ w3)
{
    __shared__ float sk[NH * WID];
    __shared__ float tile[32][33];
    const int tid = threadIdx.x;

    if (blockIdx.x < 2048) {
        for (int i = tid; i < NH * WID; i += 256) sk[i] = lrk[i];
        __syncthreads();
        const int gw = blockIdx.x * 8 + (tid >> 5);
        const int lane = tid & 31;
        const float* hrow = hidden + (size_t)gw * WID;
        float acc[NH];
#pragma unroll
        for (int h = 0; h < NH; h++) acc[h] = 0.f;
        for (int w = lane; w < WID; w += 32) {
            float hv = hrow[w];
#pragma unroll
            for (int h = 0; h < NH; h++) acc[h] += hv * sk[h * WID + w];
        }
        const int b = gw >> 12, n = gw & (SEQ - 1);
#pragma unroll
        for (int h = 0; h < NH; h++) {
            float v = wred(acc[h]);
            if (lane == 0) {
                float x = v + lrb[h];
                g_lr[(size_t)(b * NH + h) * SEQ + n] = (1.f / (1.f + expf(-x))) * (1.f / 64.f);
            }
        }
    } else if (blockIdx.x < 2048 + 4 * 576) {
        const int bi = blockIdx.x - 2048;
        const int z = bi / 576;
        const int rem = bi % 576;
        const float* w = (z == 0) ? w0 : (z == 1) ? w1 : (z == 2) ? w2 : w3;
        __half* th = g_wt + (size_t)z * WW;
        const int bx = (rem % 24) * 32;
        const int by = (rem / 24) * 32;
        const int x = tid & 31, y = tid >> 5;
#pragma unroll
        for (int j = 0; j < 4; j++)
            tile[y + j * 8][x] = w[(size_t)(by + y + j * 8) * WID + bx + x];
        __syncthreads();
#pragma unroll
        for (int j = 0; j < 4; j++) {
            float v = tile[x][y + j * 8];
            th[(size_t)(bx + y + j * 8) * WID + by + x] = __float2half_rn(v);
        }
    } else {
        const int i = (blockIdx.x - 2048 - 4 * 576) * 256 + tid;
        float4 v = ((const float4*)hidden)[i];
        ((uint2*)g_hh)[i] = make_uint2(packh2(v.x, v.y), packh2(v.z, v.w));
    }
}

// ------------------------- fp16 GEMM via mma.sync, BK=64 ---------------------
#define TSTRIDE 72
#define TILEB  (128*TSTRIDE*2)
#define STAGEB (2*TILEB)

__global__ __launch_bounds__(256) void mma_gemm_kernel(
    const __half* __restrict__ Ah, const __half* __restrict__ Bh,
    float* __restrict__ C0, float* __restrict__ C1, float* __restrict__ C2)
{
    extern __shared__ char smem[];
    const uint32_t sb = smem_u32(smem);
    const int tid = threadIdx.x, wid = tid >> 5, lane = tid & 31;
    const int bm = blockIdx.y * 128;
    const int bn = blockIdx.x * 128;
    const int buf = blockIdx.x / 6;
    const int coloff = (blockIdx.x % 6) * 128;
    float* C = (buf == 0) ? C0 : (buf == 1) ? C1 : C2;
    const int warpM = wid & 3, warpN = wid >> 2;

    const __half* srcs[2] = { Ah + (size_t)bm * WID, Bh + (size_t)bn * WID };

    auto load_stage = [&](int st, int k0) {
#pragma unroll
        for (int t = 0; t < 2; t++) {
#pragma unroll
            for (int rep = 0; rep < 4; rep++) {
                int li = tid + rep * 256;
                int row = li >> 3, cc = li & 7;
                const void* g = srcs[t] + (size_t)row * WID + k0 + cc * 8;
                uint32_t sa = sb + st * STAGEB + t * TILEB + row * (TSTRIDE * 2) + cc * 16;
                cpa16(sa, g);
            }
        }
        cpa_commit();
    };

    float acc[2][8][4];
#pragma unroll
    for (int i = 0; i < 2; i++)
#pragma unroll
        for (int j = 0; j < 8; j++)
#pragma unroll
            for (int k = 0; k < 4; k++) acc[i][j][k] = 0.f;

    load_stage(0, 0);

    const int NK = WID / 64;
    for (int kt = 0; kt < NK; kt++) {
        asm volatile("cp.async.wait_group 0;" ::: "memory");
        __syncthreads();
        if (kt + 1 < NK) load_stage((kt + 1) & 1, (kt + 1) * 64);

        const uint32_t base = sb + (kt & 1) * STAGEB;
        const int lrow = lane & 15;
        const int lcol = (lane & 16) ? 8 : 0;

#pragma unroll
        for (int kk = 0; kk < 4; kk++) {
            const int kb = kk * 16;
            uint32_t ah[2][4], bhf[8][2];
#pragma unroll
            for (int mt = 0; mt < 2; mt++) {
                uint32_t off = (uint32_t)((warpM * 32 + mt * 16 + lrow) * TSTRIDE + kb + lcol) * 2;
                ldsm4(ah[mt][0], ah[mt][1], ah[mt][2], ah[mt][3], base + off);
            }
#pragma unroll
            for (int ng = 0; ng < 4; ng++) {
                uint32_t off = (uint32_t)((warpN * 64 + ng * 16 + lrow) * TSTRIDE + kb + lcol) * 2;
                uint32_t r0, r1, r2, r3;
                ldsm4(r0, r1, r2, r3, base + TILEB + off);
                bhf[ng * 2][0] = r0; bhf[ng * 2 + 1][0] = r1;
                bhf[ng * 2][1] = r2; bhf[ng * 2 + 1][1] = r3;
            }
#pragma unroll
            for (int mt = 0; mt < 2; mt++)
#pragma unroll
                for (int nt = 0; nt < 8; nt++)
                    mma16816h(acc[mt][nt], ah[mt], bhf[nt]);
        }
    }

    const int r0 = bm + warpM * 32 + (lane >> 2);
    const int cb = coloff + warpN * 64 + 2 * (lane & 3);
#pragma unroll
    for (int mt = 0; mt < 2; mt++)
#pragma unroll
        for (int nt = 0; nt < 8; nt++) {
            int row = r0 + mt * 16, col = cb + nt * 8;
            *(float2*)(C + (size_t)row * WID + col) = make_float2(acc[mt][nt][0], acc[mt][nt][1]);
            *(float2*)(C + (size_t)(row + 8) * WID + col) = make_float2(acc[mt][nt][2], acc[mt][nt][3]);
        }
}

// ------------------------- TTT scan (256 threads, 3 barriers/step) ----------
// Proven-best (R15): double-buffered tiles, separate Attn phase, no fp32 sG.
#define SCAN_SMEM (4496*4 + (2*4608 + 2*4*1152 + 4*1152 + 2*384)*2)

__global__ __launch_bounds__(256) void ttt_scan_kernel(
    const float* __restrict__ W1in, const float* __restrict__ b1in,
    const float* __restrict__ gin,  const float* __restrict__ bbin,
    const float* __restrict__ lti,
    const float* __restrict__ cqk, const float* __restrict__ cqb,
    const float* __restrict__ ckk, const float* __restrict__ ckb)
{
    extern __shared__ float sm[];
    float* sZ   = sm + 1088;          // [16][68]
    float* sZbB = sm + 2176;          // [2][16][68]
    float* b1s  = sm + 4352;          // [64]
    float* lrB  = sm + 4416;          // [2][16]
    float* lrwB = sm + 4448;          // [2][16]
    float* toki = sm + 4480;          // [16]
    __nv_bfloat16* W1h = (__nv_bfloat16*)(sm + 4496);  // [64 k][72 d]
    __nv_bfloat16* W1l = W1h + 4608;
    __nv_bfloat16* KQ  = W1l + 4608;                   // [2][4][16*72]
    __nv_bfloat16* sPh = KQ + 2 * 4608;
    __nv_bfloat16* sPl = sPh + 1152;
    __nv_bfloat16* sWGh= sPl + 1152;
    __nv_bfloat16* sWGl= sWGh + 1152;
    __nv_bfloat16* CfH = sWGl + 1152;                  // [16 i][24 m]
    __nv_bfloat16* CfL = CfH + 384;

    const uint32_t uKQ0 = smem_u32(KQ);
    const uint32_t uKQ1 = uKQ0 + 4608 * 2;
    const uint32_t uWh = smem_u32(W1h), uWl = smem_u32(W1l);
    const uint32_t uPh = smem_u32(sPh), uPl = smem_u32(sPl);
    const uint32_t uGh = smem_u32(sWGh), uGl = smem_u32(sWGl);
    const uint32_t uCfH = smem_u32(CfH), uCfL = smem_u32(CfL);

    const int tid = threadIdx.x;
    const int bh = blockIdx.x;
    const int b = bh / NH, h = bh % NH;
    const int lane = tid & 31, wid = tid >> 5;
    const int r  = tid >> 4;
    const int cg = tid & 15;
    const int c0 = cg * 4;

    for (int i = tid; i < 4096; i += 256) {
        int k = i >> 6, d = i & 63;
        float v = W1in[h * 4096 + i];
        __nv_bfloat16 hi = __float2bfloat16(v);
        W1h[k * 72 + d] = hi;
        W1l[k * 72 + d] = __float2bfloat16(v - __bfloat162float(hi));
    }
    if (tid < 64) b1s[tid] = b1in[h * 64 + tid];
    if (tid < 16) toki[tid] = fmaxf(1.f / (float)(tid + 1) + lti[tid], 0.f);

    const int n0w = wid * 8;
    const int krw = lane >> 2;
    const int dcw = n0w + 2 * (lane & 3);
    const int drow = lane >> 2;
    float cw[4][4];
#pragma unroll
    for (int mt = 0; mt < 4; mt++) {
        const float* wsrc = W1in + h * 4096 + (mt * 16 + krw) * 64 + dcw;
        cw[mt][0] = wsrc[0];        cw[mt][1] = wsrc[1];
        cw[mt][2] = wsrc[8 * 64];   cw[mt][3] = wsrc[8 * 64 + 1];
    }

    const size_t gb2 = (size_t)b * SEQ * WID + h * 64 + c0;
    const float* lrp = g_lr + (size_t)bh * SEQ;

    float4 wq0 = *(const float4*)(cqk + 0 * WID + h * 64 + c0);
    float4 wq1 = *(const float4*)(cqk + 1 * WID + h * 64 + c0);
    float4 wq2 = *(const float4*)(cqk + 2 * WID + h * 64 + c0);
    float4 wq3 = *(const float4*)(cqk + 3 * WID + h * 64 + c0);
    float4 wk0 = *(const float4*)(ckk + 0 * WID + h * 64 + c0);
    float4 wk1 = *(const float4*)(ckk + 1 * WID + h * 64 + c0);
    float4 wk2 = *(const float4*)(ckk + 2 * WID + h * 64 + c0);
    float4 wk3 = *(const float4*)(ckk + 3 * WID + h * 64 + c0);
    float4 qb4 = *(const float4*)(cqb + h * 64 + c0);
    float4 kb4 = *(const float4*)(ckb + h * 64 + c0);
    int j0 = c0 >> 1;
    float f0 = expf(-9.210340371976184f * (float)j0 * (1.f / 32.f));
    float f1 = expf(-9.210340371976184f * (float)(j0 + 1) * (1.f / 32.f));
    const float cs0 = cosf((float)r * f0), sn0 = sinf((float)r * f0);
    const float cs1 = cosf((float)r * f1), sn1 = sinf((float)r * f1);
    const float gv0 = gin[h * 64 + c0],     gv1 = gin[h * 64 + c0 + 1];
    const float gv2 = gin[h * 64 + c0 + 2], gv3 = gin[h * 64 + c0 + 3];
    const float bv0 = bbin[h * 64 + c0],     bv1 = bbin[h * 64 + c0 + 1];
    const float bv2 = bbin[h * 64 + c0 + 2], bv3 = bbin[h * 64 + c0 + 3];

    __syncthreads();
    const float toki15 = toki[15];

    float4 x0n = make_float4(0, 0, 0, 0), x1n = x0n, x2n = x0n, x3n = x0n;
    if (r >= 3) x0n = *(const float4*)(g_xqk + gb2 + (size_t)(r - 3) * WID);
    if (r >= 2) x1n = *(const float4*)(g_xqk + gb2 + (size_t)(r - 2) * WID);
    if (r >= 1) x2n = *(const float4*)(g_xqk + gb2 + (size_t)(r - 1) * WID);
    x3n = *(const float4*)(g_xqk + gb2 + (size_t)r * WID);
    float4 v4n = *(const float4*)(g_xv + gb2 + (size_t)r * WID);
    float lrn = (tid < 16) ? lrp[tid] : 0.f;

    float4 q4c, t4c, q4prev = make_float4(0, 0, 0, 0);
    uint32_t kp0, kp1, klp0, klp1, qp0, qp1, qlp0, qlp1;
    {
        float4 q, k;
        q.x = qb4.x + x0n.x * wq0.x + x1n.x * wq1.x + x2n.x * wq2.x + x3n.x * wq3.x;
        q.y = qb4.y + x0n.y * wq0.y + x1n.y * wq1.y + x2n.y * wq2.y + x3n.y * wq3.y;
        q.z = qb4.z + x0n.z * wq0.z + x1n.z * wq1.z + x2n.z * wq2.z + x3n.z * wq3.z;
        q.w = qb4.w + x0n.w * wq0.w + x1n.w * wq1.w + x2n.w * wq2.w + x3n.w * wq3.w;
        k.x = kb4.x + x0n.x * wk0.x + x1n.x * wk1.x + x2n.x * wk2.x + x3n.x * wk3.x;
        k.y = kb4.y + x0n.y * wk0.y + x1n.y * wk1.y + x2n.y * wk2.y + x3n.y * wk3.y;
        k.z = kb4.z + x0n.z * wk0.z + x1n.z * wk1.z + x2n.z * wk2.z + x3n.z * wk3.z;
        k.w = kb4.w + x0n.w * wk0.w + x1n.w * wk1.w + x2n.w * wk2.w + x3n.w * wk3.w;
        float4 qr, kr;
        qr.x = q.x * cs0 - q.y * sn0; qr.y = q.x * sn0 + q.y * cs0;
        qr.z = q.z * cs1 - q.w * sn1; qr.w = q.z * sn1 + q.w * cs1;
        kr.x = k.x * cs0 - k.y * sn0; kr.y = k.x * sn0 + k.y * cs0;
        kr.z = k.z * cs1 - k.w * sn1; kr.w = k.z * sn1 + k.w * cs1;
        kp0 = pack2(kr.x, kr.y); kp1 = pack2(kr.z, kr.w);
        klp0 = pack2(kr.x - bflo(kp0), kr.y - bfhi(kp0));
        klp1 = pack2(kr.z - bflo(kp1), kr.w - bfhi(kp1));
        qp0 = pack2(qr.x, qr.y); qp1 = pack2(qr.z, qr.w);
        qlp0 = pack2(qr.x - bflo(qp0), qr.y - bfhi(qp0));
        qlp1 = pack2(qr.z - bflo(qp1), qr.w - bfhi(qp1));
        q4c = qr;
        t4c = make_float4(v4n.x - kr.x, v4n.y - kr.y, v4n.z - kr.z, v4n.w - kr.w);
    }

    for (int nb = 0; nb < NBt; nb++) {
        const int buf = nb & 1;
        const uint32_t uB  = buf ? uKQ1 : uKQ0;
        const uint32_t uKh = uB, uKl = uB + 1152 * 2;
        const uint32_t uQh = uB + 2304 * 2, uQl = uB + 3456 * 2;
        __nv_bfloat16* sKh = KQ + buf * 4608;
        __nv_bfloat16* sKl = sKh + 1152;
        __nv_bfloat16* sQh = sKl + 1152;
        __nv_bfloat16* sQl = sQh + 1152;
        float* lr  = lrB  + buf * 16;
        float* lrw = lrwB + buf * 16;
        float* sZb = sZbB + buf * 1088;
        float* sZbPrev = sZbB + (buf ^ 1) * 1088;

        *(uint2*)(sKh + r * 72 + c0) = make_uint2(kp0, kp1);
        *(uint2*)(sKl + r * 72 + c0) = make_uint2(klp0, klp1);
        *(uint2*)(sQh + r * 72 + c0) = make_uint2(qp0, qp1);
        *(uint2*)(sQl + r * 72 + c0) = make_uint2(qlp0, qlp1);
        if (tid < 16) { lr[tid] = lrn; lrw[tid] = toki15 * lrn; }
        if (nb > 0) {
            float4 y4 = *(const float4*)(sZbPrev + r * 68 + c0);
            float s = hred(y4.x + y4.y + y4.z + y4.w);
            float qq = hred(y4.x * y4.x + y4.y * y4.y + y4.z * y4.z + y4.w * y4.w);
            float m = s * (1.f / 64.f);
            float rstd = rsqrtf(qq * (1.f / 64.f) - m * m + EPSV);
            float4 o;
            o.x = q4prev.x + gv0 * ((y4.x - m) * rstd) + bv0;
            o.y = q4prev.y + gv1 * ((y4.y - m) * rstd) + bv1;
            o.z = q4prev.z + gv2 * ((y4.z - m) * rstd) + bv2;
            o.w = q4prev.w + gv3 * ((y4.w - m) * rstd) + bv3;
            *(float4*)(g_ttt + gb2 + (size_t)((nb - 1) * MBm + r) * WID) = o;
        }
        __syncthreads();                                   // (B)

        if (nb + 1 < NBt) {
            const size_t rb = gb2 + (size_t)((nb + 1) * MBm + r - 3) * WID;
            x0n = *(const float4*)(g_xqk + rb);
            x1n = *(const float4*)(g_xqk + rb + WID);
            x2n = *(const float4*)(g_xqk + rb + 2 * WID);
            x3n = *(const float4*)(g_xqk + rb + 3 * WID);
            v4n = *(const float4*)(g_xv + rb + 3 * WID);
            if (tid < 16) lrn = lrp[(nb + 1) * MBm + tid];
        }

        // Z GEMM: zk -> sZ ; zq stays in registers
        float zq[4];
        {
            float zk[4];
            float bA = b1s[dcw], bB = b1s[dcw + 1];
            zk[0] = bA; zk[1] = bB; zk[2] = bA; zk[3] = bB;
            zq[0] = bA; zq[1] = bB; zq[2] = bA; zq[3] = bB;
            const int la = lane & 15;
#pragma unroll
            for (int ks = 0; ks < 4; ks++) {
                const int kb = ks * 16;
                uint32_t aoff = (uint32_t)(la * 72 + kb + (lane >> 4) * 8) * 2;
                uint32_t boff = (uint32_t)((kb + la) * 72 + n0w) * 2;
                uint32_t akh[4], akl[4], aqh[4], aql[4], bhf[2], blf[2];
                ldsm4(akh[0], akh[1], akh[2], akh[3], uKh + aoff);
                ldsm4(akl[0], akl[1], akl[2], akl[3], uKl + aoff);
                ldsm4(aqh[0], aqh[1], aqh[2], aqh[3], uQh + aoff);
                ldsm4(aql[0], aql[1], aql[2], aql[3], uQl + aoff);
                ldsm2t(bhf[0], bhf[1], uWh + boff);
                ldsm2t(blf[0], blf[1], uWl + boff);
                mma16816(zk, akh, bhf);
                mma16816(zk, akh, blf);
                mma16816(zk, akl, bhf);
                mma16816(zq, aqh, bhf);
                mma16816(zq, aqh, blf);
                mma16816(zq, aql, bhf);
            }
            *(float2*)(sZ + drow * 68 + dcw)       = make_float2(zk[0], zk[1]);
            *(float2*)(sZ + (drow + 8) * 68 + dcw) = make_float2(zk[2], zk[3]);
        }

        // Attn + Cf on warps 0,1: Cf_raw = toki[i]*(Attn+1)*mask
        if (wid < 2) {
            float at[4] = {0.f, 0.f, 0.f, 0.f};
            const int la = lane & 15;
#pragma unroll
            for (int ks = 0; ks < 4; ks++) {
                uint32_t off = (uint32_t)(la * 72 + ks * 16 + (lane >> 4) * 8) * 2;
                uint32_t qh4[4], ql4[4], kh4[4], kl4[4];
                ldsm4(qh4[0], qh4[1], qh4[2], qh4[3], uQh + off);
                ldsm4(ql4[0], ql4[1], ql4[2], ql4[3], uQl + off);
                ldsm4(kh4[0], kh4[1], kh4[2], kh4[3], uKh + off);
                ldsm4(kl4[0], kl4[1], kl4[2], kl4[3], uKl + off);
                uint32_t bhh[2] = { kh4[wid], kh4[wid + 2] };
                uint32_t bll[2] = { kl4[wid], kl4[wid + 2] };
                mma16816(at, qh4, bhh);
                mma16816(at, qh4, bll);
                mma16816(at, ql4, bhh);
            }
            const int i0 = lane >> 2;
            const int m0 = wid * 8 + 2 * (lane & 3);
            float ta = toki[i0], tb = toki[i0 + 8];
            float v00 = (m0     <= i0    ) ? ta * (at[0] + 1.f) : 0.f;
            float v01 = (m0 + 1 <= i0    ) ? ta * (at[1] + 1.f) : 0.f;
            float v10 = (m0     <= i0 + 8) ? tb * (at[2] + 1.f) : 0.f;
            float v11 = (m0 + 1 <= i0 + 8) ? tb * (at[3] + 1.f) : 0.f;
            uint32_t h0 = pack2(v00, v01), h1 = pack2(v10, v11);
            *(uint32_t*)(CfH + i0 * 24 + m0)       = h0;
            *(uint32_t*)(CfH + (i0 + 8) * 24 + m0) = h1;
            *(uint32_t*)(CfL + i0 * 24 + m0)       = pack2(v00 - bflo(h0), v01 - bfhi(h0));
            *(uint32_t*)(CfL + (i0 + 8) * 24 + m0) = pack2(v10 - bflo(h1), v11 - bfhi(h1));
        }
        __syncthreads();                                   // (B2)

        // LN-fused-L2-bwd; pack two bf16 grad tile sets (no fp32 sG)
        {
            float4 z4 = *(const float4*)(sZ + r * 68 + c0);
            float z0 = z4.x, z1 = z4.y, z2 = z4.z, z3 = z4.w;
            float s = hred(z0 + z1 + z2 + z3);
            float qq = hred(z0 * z0 + z1 * z1 + z2 * z2 + z3 * z3);
            float m = s * (1.f / 64.f);
            float rstd = rsqrtf(qq * (1.f / 64.f) - m * m + EPSV);
            float xh0 = (z0 - m) * rstd, xh1 = (z1 - m) * rstd;
            float xh2 = (z2 - m) * rstd, xh3 = (z3 - m) * rstd;
            float gx0 = (gv0 * xh0 + bv0 - t4c.x) * gv0;
            float gx1 = (gv1 * xh1 + bv1 - t4c.y) * gv1;
            float gx2 = (gv2 * xh2 + bv2 - t4c.z) * gv2;
            float gx3 = (gv3 * xh3 + bv3 - t4c.w) * gv3;
            float s1 = hred(gx0 + gx1 + gx2 + gx3);
            float s2 = hred(gx0 * xh0 + gx1 * xh1 + gx2 * xh2 + gx3 * xh3);
            float sc = rstd * (1.f / 64.f);
            float grx = (64.f * gx0 - s1 - xh0 * s2) * sc;
            float gry = (64.f * gx1 - s1 - xh1 * s2) * sc;
            float grz = (64.f * gx2 - s1 - xh2 * s2) * sc;
            float grw = (64.f * gx3 - s1 - xh3 * s2) * sc;
            float lrr = lr[r];
            float p0 = -lrr * grx, p1 = -lrr * gry, p2 = -lrr * grz, p3 = -lrr * grw;
            uint32_t ph0 = pack2(p0, p1), ph1 = pack2(p2, p3);
            *(uint2*)(sPh + r * 72 + c0) = make_uint2(ph0, ph1);
            *(uint2*)(sPl + r * 72 + c0) = make_uint2(
                pack2(p0 - bflo(ph0), p1 - bfhi(ph0)),
                pack2(p2 - bflo(ph1), p3 - bfhi(ph1)));
            float w0 = toki15 * p0, w1 = toki15 * p1, w2 = toki15 * p2, w3 = toki15 * p3;
            uint32_t wh0 = pack2(w0, w1), wh1 = pack2(w2, w3);
            *(uint2*)(sWGh + r * 72 + c0) = make_uint2(wh0, wh1);
            *(uint2*)(sWGl + r * 72 + c0) = make_uint2(
                pack2(w0 - bflo(wh0), w1 - bfhi(wh0)),
                pack2(w2 - bflo(wh1), w3 - bfhi(wh1)));
        }
        __syncthreads();                                   // (C)

        // Z1_bar = zq + Cf_raw @ (-lr*grad)
        {
            uint32_t cfh4[4], cfl4[4], bp[2], bpl[2];
            uint32_t aoffc = (uint32_t)((lane & 15) * 24 + (lane >> 4) * 8) * 2;
            ldsm4(cfh4[0], cfh4[1], cfh4[2], cfh4[3], uCfH + aoffc);
            ldsm4(cfl4[0], cfl4[1], cfl4[2], cfl4[3], uCfL + aoffc);
            uint32_t boffp = (uint32_t)((lane & 15) * 72 + n0w) * 2;
            ldsm2t(bp[0], bp[1], uPh + boffp);
            ldsm2t(bpl[0], bpl[1], uPl + boffp);
            mma16816(zq, cfh4, bp);
            mma16816(zq, cfh4, bpl);
            mma16816(zq, cfl4, bp);
            *(float2*)(sZb + drow * 68 + dcw)       = make_float2(zq[0], zq[1]);
            *(float2*)(sZb + (drow + 8) * 68 + dcw) = make_float2(zq[2], zq[3]);
        }

        // W1 update: cw += XK^T @ (-toki15*lr*grad); bf16 writeback
        {
            uint32_t bgh[2], bgl[2];
            const uint32_t gboff = (uint32_t)((lane & 15) * 72 + n0w) * 2;
            ldsm2t(bgh[0], bgh[1], uGh + gboff);
            ldsm2t(bgl[0], bgl[1], uGl + gboff);
            const int amr = ((lane >> 4) << 3) + (lane & 7);
            const int akc = ((lane >> 3) & 1) << 3;
#pragma unroll
            for (int mt = 0; mt < 4; mt++) {
                uint32_t aoff = (uint32_t)(amr * 72 + mt * 16 + akc) * 2;
                uint32_t akh[4], akl[4];
                ldsm4t(akh[0], akh[1], akh[2], akh[3], uKh + aoff);
                ldsm4t(akl[0], akl[1], akl[2], akl[3], uKl + aoff);
                mma16816(cw[mt], akh, bgh);
                mma16816(cw[mt], akh, bgl);
                mma16816(cw[mt], akl, bgh);
            }
#pragma unroll
            for (int mt = 0; mt < 4; mt++) {
                int k0 = mt * 16 + krw;
                uint32_t h01 = pack2(cw[mt][0], cw[mt][1]);
                uint32_t h23 = pack2(cw[mt][2], cw[mt][3]);
                *(uint32_t*)(W1h + k0 * 72 + dcw)       = h01;
                *(uint32_t*)(W1h + (k0 + 8) * 72 + dcw) = h23;
                *(uint32_t*)(W1l + k0 * 72 + dcw) = pack2(
                    cw[mt][0] - bflo(h01), cw[mt][1] - bfhi(h01));
                *(uint32_t*)(W1l + (k0 + 8) * 72 + dcw) = pack2(
                    cw[mt][2] - bflo(h23), cw[mt][3] - bfhi(h23));
            }
            // b1 += colsum(WG) — threads 0..63
            if (tid < 64) {
                const int du = tid;
                float bs = 0.f;
#pragma unroll
                for (int mm = 0; mm < 16; mm++) {
                    bs += __bfloat162float(sWGh[mm * 72 + du]);
                    bs += __bfloat162float(sWGl[mm * 72 + du]);
                }
                b1s[du] += bs;
            }
        }

        // conv/rope for nb+1 (registers only)
        q4prev = q4c;
        if (nb + 1 < NBt) {
            float4 q, k;
            q.x = qb4.x + x0n.x * wq0.x + x1n.x * wq1.x + x2n.x * wq2.x + x3n.x * wq3.x;
            q.y = qb4.y + x0n.y * wq0.y + x1n.y * wq1.y + x2n.y * wq2.y + x3n.y * wq3.y;
            q.z = qb4.z + x0n.z * wq0.z + x1n.z * wq1.z + x2n.z * wq2.z + x3n.z * wq3.z;
            q.w = qb4.w + x0n.w * wq0.w + x1n.w * wq1.w + x2n.w * wq2.w + x3n.w * wq3.w;
            k.x = kb4.x + x0n.x * wk0.x + x1n.x * wk1.x + x2n.x * wk2.x + x3n.x * wk3.x;
            k.y = kb4.y + x0n.y * wk0.y + x1n.y * wk1.y + x2n.y * wk2.y + x3n.y * wk3.y;
            k.z = kb4.z + x0n.z * wk0.z + x1n.z * wk1.z + x2n.z * wk2.z + x3n.z * wk3.z;
            k.w = kb4.w + x0n.w * wk0.w + x1n.w * wk1.w + x2n.w * wk2.w + x3n.w * wk3.w;
            float4 qr, kr;
            qr.x = q.x * cs0 - q.y * sn0; qr.y = q.x * sn0 + q.y * cs0;
            qr.z = q.z * cs1 - q.w * sn1; qr.w = q.z * sn1 + q.w * cs1;
            kr.x = k.x * cs0 - k.y * sn0; kr.y = k.x * sn0 + k.y * cs0;
            kr.z = k.z * cs1 - k.w * sn1; kr.w = k.z * sn1 + k.w * cs1;
            kp0 = pack2(kr.x, kr.y); kp1 = pack2(kr.z, kr.w);
            klp0 = pack2(kr.x - bflo(kp0), kr.y - bfhi(kp0));
            klp1 = pack2(kr.z - bflo(kp1), kr.w - bfhi(kp1));
            qp0 = pack2(qr.x, qr.y); qp1 = pack2(qr.z, qr.w);
            qlp0 = pack2(qr.x - bflo(qp0), qr.y - bfhi(qp0));
            qlp1 = pack2(qr.z - bflo(qp1), qr.w - bfhi(qp1));
            q4c = qr;
            t4c = make_float4(v4n.x - kr.x, v4n.y - kr.y, v4n.z - kr.z, v4n.w - kr.w);
        }
    }

    // final output (nb = NBt-1, buffer (NBt-1)&1 = 1)
    __syncthreads();
    {
        float* sZbF = sZbB + ((NBt - 1) & 1) * 1088;
        float4 y4 = *(const float4*)(sZbF + r * 68 + c0);
        float s = hred(y4.x + y4.y + y4.z + y4.w);
        float qq = hred(y4.x * y4.x + y4.y * y4.y + y4.z * y4.z + y4.w * y4.w);
        float m = s * (1.f / 64.f);
        float rstd = rsqrtf(qq * (1.f / 64.f) - m * m + EPSV);
        float4 o;
        o.x = q4prev.x + gv0 * ((y4.x - m) * rstd) + bv0;
        o.y = q4prev.y + gv1 * ((y4.y - m) * rstd) + bv1;
        o.z = q4prev.z + gv2 * ((y4.z - m) * rstd) + bv2;
        o.w = q4prev.w + gv3 * ((y4.w - m) * rstd) + bv3;
        *(float4*)(g_ttt + gb2 + (size_t)((NBt - 1) * MBm + r) * WID) = o;
    }
}

// ------------- post: warp-per-row, no block barriers -------------------------
__global__ __launch_bounds__(256) void postfuse_kernel(
    const float* __restrict__ pns, const float* __restrict__ pnb)
{
    const int lane = threadIdx.x & 31;
    const int row = blockIdx.x * 8 + (threadIdx.x >> 5);
    const float4* o4 = (const float4*)(g_ttt + (size_t)row * WID);
    const float4* g4 = (const float4*)(g_gate + (size_t)row * WID);
    uint2* t2 = (uint2*)(g_th + (size_t)row * WID);

    float4 v[6];
    float s = 0.f, q = 0.f;
#pragma unroll
    for (int i = 0; i < 6; i++) {
        v[i] = o4[lane + 32 * i];
        s += v[i].x + v[i].y + v[i].z + v[i].w;
        q += v[i].x * v[i].x + v[i].y * v[i].y + v[i].z * v[i].z + v[i].w * v[i].w;
    }
    s = wred(s); q = wred(q);
    const float m = s * (1.f / 768.f);
    const float rs = rsqrtf(q * (1.f / 768.f) - m * m + EPSV);

#pragma unroll
    for (int i = 0; i < 6; i++) {
        const int c = (lane + 32 * i) * 4;
        float4 pn = *(const float4*)(pns + c);
        float4 pb = *(const float4*)(pnb + c);
        float4 g = g4[lane + 32 * i];
        float z0 = pn.x * ((v[i].x - m) * rs) + pb.x;
        float z1 = pn.y * ((v[i].y - m) * rs) + pb.y;
        float z2 = pn.z * ((v[i].z - m) * rs) + pb.z;
        float z3 = pn.w * ((v[i].w - m) * rs) + pb.w;
        float gl0 = 0.5f * g.x * (1.f + tanhf(0.7978845608028654f * (g.x + 0.044715f * g.x * g.x * g.x)));
        float gl1 = 0.5f * g.y * (1.f + tanhf(0.7978845608028654f * (g.y + 0.044715f * g.y * g.y * g.y)));
        float gl2 = 0.5f * g.z * (1.f + tanhf(0.7978845608028654f * (g.z + 0.044715f * g.z * g.z * g.z)));
        float gl3 = 0.5f * g.w * (1.f + tanhf(0.7978845608028654f * (g.w + 0.044715f * g.w * g.w * g.w)));
        t2[lane + 32 * i] = make_uint2(packh2(gl0 * z0, gl1 * z1), packh2(gl2 * z2, gl3 * z3));
    }
}

// ------------------------- launch --------------------------------------------
extern "C" void kernel_launch(void* const* d_in, const int* in_sizes, int n_in,
                              void* d_out, int out_size)
{
    const float* hidden = (const float*)d_in[0];
    const float* wq  = (const float*)d_in[1];
    const float* wv  = (const float*)d_in[2];
    const float* wo  = (const float*)d_in[3];
    const float* wg  = (const float*)d_in[4];
    const float* cqk = (const float*)d_in[5];
    const float* cqb = (const float*)d_in[6];
    const float* ckk = (const float*)d_in[7];
    const float* ckb = (const float*)d_in[8];
    const float* W1  = (const float*)d_in[9];
    const float* b1  = (const float*)d_in[10];
    const float* tns = (const float*)d_in[11];
    const float* tnb = (const float*)d_in[12];
    const float* lrk = (const float*)d_in[13];
    const float* lrb = (const float*)d_in[14];
    const float* lti = (const float*)d_in[15];
    const float* pns = (const float*)d_in[16];
    const float* pnb = (const float*)d_in[17];
    float* out = (float*)d_out;

    float *p_xqk, *p_xv, *p_gate;
    __half *p_hh, *p_th, *p_wt;
    cudaGetSymbolAddress((void**)&p_xqk,  g_xqk);
    cudaGetSymbolAddress((void**)&p_xv,   g_xv);
    cudaGetSymbolAddress((void**)&p_gate, g_gate);
    cudaGetSymbolAddress((void**)&p_hh,   g_hh);
    cudaGetSymbolAddress((void**)&p_th,   g_th);
    cudaGetSymbolAddress((void**)&p_wt,   g_wt);

    const int smem_mma = 2 * STAGEB;   // 73728
    cudaFuncSetAttribute(mma_gemm_kernel, cudaFuncAttributeMaxDynamicSharedMemorySize, smem_mma);
    cudaFuncSetAttribute(ttt_scan_kernel, cudaFuncAttributeMaxDynamicSharedMemorySize, SCAN_SMEM);

    // 1: lr + weight cvt + hidden cvt fused
    prep_kernel<<<2048 + 4 * 576 + MTOT * WID / 4 / 256, 256>>>(
        hidden, lrk, lrb, wq, wv, wg, wo);
    // 2: fused QVG GEMM
    {
        dim3 gg(18, MTOT / 128);
        mma_gemm_kernel<<<gg, 256, smem_mma>>>(p_hh, p_wt, p_xqk, p_xv, p_gate);
    }
    // 3: scan
    ttt_scan_kernel<<<Bsz * NH, 256, SCAN_SMEM>>>(W1, b1, tns, tnb, lti, cqk, cqb, ckk, ckb);
    // 4: post LN * gelu gate (warp-per-row)
    postfuse_kernel<<<MTOT / 8, 256>>>(pns, pnb);
    // 5: output GEMM
    {
        dim3 gg(6, MTOT / 128);
        mma_gemm_kernel<<<gg, 256, smem_mma>>>(p_th, p_wt + (size_t)3 * WW, out, out, out);
    }
}